// round 15
// baseline (speedup 1.0000x reference)
#include <cuda_runtime.h>

// out[s,:] = W_tok[x[s],:] + b_tok + W_pos[(S-1)-s,:] + b_pos
// S=8192, D=1024 fp32.
// R14: R7 chassis byte-for-byte (persistent single-wave, 888 CTAs, depth-1
// register pipeline = 12.8us best) + data-less depth-2 via prefetch.global.L2.
// Depth helped in principle (R9) but register cost killed it; prefetch buys
// distance-2 with zero data regs. One prefetch per 128B line ((t&7)==0 lanes).

constexpr int SEQ   = 8192;
constexpr int EMBED = 1024;
constexpr int VEC   = EMBED / 4;   // 256 float4 per row
constexpr int GRID  = 888;         // 148 SMs x 6 CTAs -> exactly one wave

__device__ __forceinline__ void prefetch_l2(const void* p) {
    asm volatile("prefetch.global.L2 [%0];" :: "l"(p));
}

__global__ __launch_bounds__(256, 6)
void linear_embedding_kernel(const int* __restrict__ x,
                             const float4* __restrict__ W_tok,
                             const float4* __restrict__ b_tok,
                             const float4* __restrict__ W_pos,
                             const float4* __restrict__ b_pos,
                             float4* __restrict__ out)
{
    const int t      = threadIdx.x;
    const int stride = GRID;
    const bool pf    = (t & 7) == 0;   // one lane per 128B line prefetches

    // Bias for this thread's column (zeros in practice; L2-resident).
    const float4 bt = __ldg(&b_tok[t]);
    const float4 bp = __ldg(&b_pos[t]);
    float4 b;
    b.x = bt.x + bp.x; b.y = bt.y + bp.y;
    b.z = bt.z + bp.z; b.w = bt.w + bp.w;

    int s = blockIdx.x;

    // Pipeline prologue: token ids 2 stages ahead, rows 1 stage ahead.
    int s1 = min(s + stride, SEQ - 1);
    int tok0 = __ldg(&x[s]);
    int tok1 = __ldg(&x[s1]);

    float4 a0 = __ldg(&W_tok[(long long)tok0 * VEC + t]);
    float4 p0 = __ldg(&W_pos[(long long)(SEQ - 1 - s) * VEC + t]);

    while (s < SEQ) {
        const int s_next = s + stride;

        // Depth-1: load next row's data (clamped; harmless duplicate on tail).
        const int sn = min(s_next, SEQ - 1);
        float4 a1 = __ldg(&W_tok[(long long)tok1 * VEC + t]);
        float4 p1 = __ldg(&W_pos[(long long)(SEQ - 1 - sn) * VEC + t]);
        // Token id 2 stages ahead.
        const int s2 = min(s_next + stride, SEQ - 1);
        const int tok2 = __ldg(&x[s2]);

        // Depth-2 (data-less): pull row s+2*stride lines into L2 now so the
        // next iteration's depth-1 loads hit L2 instead of DRAM.
        if (pf) {
            prefetch_l2(&W_tok[(long long)tok2 * VEC + t]);
            prefetch_l2(&W_pos[(long long)(SEQ - 1 - s2) * VEC + t]);
        }

        // Consume current row.
        float4 r;
        r.x = (a0.x + p0.x) + b.x;
        r.y = (a0.y + p0.y) + b.y;
        r.z = (a0.z + p0.z) + b.z;
        r.w = (a0.w + p0.w) + b.w;
        out[(long long)s * VEC + t] = r;

        // Rotate pipeline.
        s = s_next;
        a0 = a1; p0 = p1;
        tok1 = tok2;
    }
}

extern "C" void kernel_launch(void* const* d_in, const int* in_sizes, int n_in,
                              void* d_out, int out_size)
{
    const int*    x     = (const int*)d_in[0];
    const float4* W_tok = (const float4*)d_in[1];
    const float4* b_tok = (const float4*)d_in[2];
    const float4* W_pos = (const float4*)d_in[3];
    const float4* b_pos = (const float4*)d_in[4];
    float4* out = (float4*)d_out;

    linear_embedding_kernel<<<GRID, 256>>>(x, W_tok, b_tok, W_pos, b_pos, out);
}

// round 17
// speedup vs baseline: 1.0975x; 1.0975x over previous
#include <cuda_runtime.h>

// out[s,:] = W_tok[x[s],:] + b_tok + W_pos[(S-1)-s,:] + b_pos
// S=8192, D=1024 fp32.
// R15: R7 chassis verbatim (persistent single-wave, 888 CTAs, depth-1
// register pipeline — 12.8us, best of 10 structural variants). Sole change:
// store issued FIRST in the loop body (operands ready from previous
// rotation) so the STG drains ahead of this iteration's LDGs in the LSU.

constexpr int SEQ   = 8192;
constexpr int EMBED = 1024;
constexpr int VEC   = EMBED / 4;   // 256 float4 per row
constexpr int GRID  = 888;         // 148 SMs x 6 CTAs -> exactly one wave

__global__ __launch_bounds__(256, 6)
void linear_embedding_kernel(const int* __restrict__ x,
                             const float4* __restrict__ W_tok,
                             const float4* __restrict__ b_tok,
                             const float4* __restrict__ W_pos,
                             const float4* __restrict__ b_pos,
                             float4* __restrict__ out)
{
    const int t      = threadIdx.x;
    const int stride = GRID;

    // Bias for this thread's column (zeros in practice; L2-resident).
    const float4 bt = __ldg(&b_tok[t]);
    const float4 bp = __ldg(&b_pos[t]);
    float4 b;
    b.x = bt.x + bp.x; b.y = bt.y + bp.y;
    b.z = bt.z + bp.z; b.w = bt.w + bp.w;

    int s = blockIdx.x;

    // Pipeline prologue: token ids 2 stages ahead, rows 1 stage ahead.
    int s1 = min(s + stride, SEQ - 1);
    int tok0 = __ldg(&x[s]);
    int tok1 = __ldg(&x[s1]);

    float4 a0 = __ldg(&W_tok[(long long)tok0 * VEC + t]);
    float4 p0 = __ldg(&W_pos[(long long)(SEQ - 1 - s) * VEC + t]);

    while (s < SEQ) {
        const int s_next = s + stride;

        // Consume current row first: STG operands are ready (previous
        // rotation), so the store drains ahead of this iter's loads.
        float4 r;
        r.x = (a0.x + p0.x) + b.x;
        r.y = (a0.y + p0.y) + b.y;
        r.z = (a0.z + p0.z) + b.z;
        r.w = (a0.w + p0.w) + b.w;
        out[(long long)s * VEC + t] = r;

        // Prefetch next row's data (clamped; harmless duplicate on tail).
        const int sn = min(s_next, SEQ - 1);
        float4 a1 = __ldg(&W_tok[(long long)tok1 * VEC + t]);
        float4 p1 = __ldg(&W_pos[(long long)(SEQ - 1 - sn) * VEC + t]);
        // Prefetch token id 2 stages ahead.
        const int s2 = min(s_next + stride, SEQ - 1);
        const int tok2 = __ldg(&x[s2]);

        // Rotate pipeline.
        s = s_next;
        a0 = a1; p0 = p1;
        tok1 = tok2;
    }
}

extern "C" void kernel_launch(void* const* d_in, const int* in_sizes, int n_in,
                              void* d_out, int out_size)
{
    const int*    x     = (const int*)d_in[0];
    const float4* W_tok = (const float4*)d_in[1];
    const float4* b_tok = (const float4*)d_in[2];
    const float4* W_pos = (const float4*)d_in[3];
    const float4* b_pos = (const float4*)d_in[4];
    float4* out = (float4*)d_out;

    linear_embedding_kernel<<<GRID, 256>>>(x, W_tok, b_tok, W_pos, b_pos, out);
}